// round 1
// baseline (speedup 1.0000x reference)
#include <cuda_runtime.h>
#include <cuda_bf16.h>
#include <math.h>

#define BW    4096
#define NT    49
#define DIM   192
#define HEADS 6
#define HD    32
#define HIDDEN 768
#define MROWS (BW * NT)   // 200704

// Scratch (allocation-free): lifetimes allow heavy reuse.
//  g_buf192: ln1-out -> attn-out -> ln2-out   (each lifetime disjoint)
//  g_big   : qkv (576 wide) -> mlp hidden (768 wide)
__device__ float g_buf192[(size_t)MROWS * DIM];
__device__ float g_big[(size_t)MROWS * HIDDEN];

// ---------------------------------------------------------------------------
// LayerNorm: one block (192 threads) per token row.
// ---------------------------------------------------------------------------
__global__ __launch_bounds__(DIM) void ln_kernel(
    const float* __restrict__ x, const float* __restrict__ g,
    const float* __restrict__ b, float* __restrict__ out)
{
    int row = blockIdx.x;
    int t = threadIdx.x;
    float v = x[(size_t)row * DIM + t];
    float s = v, s2 = v * v;
    #pragma unroll
    for (int o = 16; o > 0; o >>= 1) {
        s  += __shfl_down_sync(0xffffffffu, s,  o);
        s2 += __shfl_down_sync(0xffffffffu, s2, o);
    }
    __shared__ float red0[6], red1[6];
    if ((t & 31) == 0) { red0[t >> 5] = s; red1[t >> 5] = s2; }
    __syncthreads();
    if (t == 0) {
        float a = 0.f, c = 0.f;
        #pragma unroll
        for (int i = 0; i < 6; i++) { a += red0[i]; c += red1[i]; }
        red0[0] = a * (1.0f / DIM);
        red1[0] = c * (1.0f / DIM);
    }
    __syncthreads();
    float mu  = red0[0];
    float var = red1[0] - mu * mu;
    out[(size_t)row * DIM + t] = (v - mu) * rsqrtf(var + 1e-5f) * g[t] + b[t];
}

// ---------------------------------------------------------------------------
// Tiled SGEMM: C[M,N] = A[M,K] @ B[K,N] (+epilogue)
// Block tile 128x64, K-step 8, 256 threads, 8x4 per-thread microtile.
// EPI: 0 = none, 1 = bias + residual, 2 = bias + exact GELU
// All dims assumed divisible (M%128==0, N%64==0, K%8==0) — true for this problem.
// ---------------------------------------------------------------------------
template <int EPI>
__global__ __launch_bounds__(256) void gemm_kernel(
    const float* __restrict__ A, const float* __restrict__ B,
    const float* __restrict__ bias, const float* __restrict__ res,
    float* __restrict__ C, int M, int Nn, int K)
{
    __shared__ float AsT[8][128];
    __shared__ float Bs[8][64];

    int bm = blockIdx.y, bn = blockIdx.x;
    int tid = threadIdx.x;
    int tx = tid & 15, ty = tid >> 4;

    float acc[8][4] = {};

    const float* Ab = A + (size_t)bm * 128 * K;
    const float* Bb = B + bn * 64;

    int arow  = tid >> 1;          // 0..127
    int acol4 = (tid & 1) * 4;     // 0 or 4

    for (int k0 = 0; k0 < K; k0 += 8) {
        // A tile: 128x8, each thread loads one float4, stores transposed
        float4 av = *(const float4*)(Ab + (size_t)arow * K + k0 + acol4);
        AsT[acol4 + 0][arow] = av.x;
        AsT[acol4 + 1][arow] = av.y;
        AsT[acol4 + 2][arow] = av.z;
        AsT[acol4 + 3][arow] = av.w;
        // B tile: 8x64, first 128 threads load one float4 each
        if (tid < 128) {
            int br = tid >> 4;          // 0..7
            int bc = (tid & 15) * 4;    // 0..60
            float4 bv = *(const float4*)(Bb + (size_t)(k0 + br) * Nn + bc);
            *(float4*)&Bs[br][bc] = bv;
        }
        __syncthreads();
        #pragma unroll
        for (int k = 0; k < 8; k++) {
            float4 a0 = *(const float4*)&AsT[k][ty * 8];
            float4 a1 = *(const float4*)&AsT[k][ty * 8 + 4];
            float4 bv = *(const float4*)&Bs[k][tx * 4];
            float aa[8] = {a0.x, a0.y, a0.z, a0.w, a1.x, a1.y, a1.z, a1.w};
            float bb[4] = {bv.x, bv.y, bv.z, bv.w};
            #pragma unroll
            for (int i = 0; i < 8; i++)
                #pragma unroll
                for (int j = 0; j < 4; j++)
                    acc[i][j] += aa[i] * bb[j];
        }
        __syncthreads();
    }

    int rowbase = bm * 128 + ty * 8;
    int colbase = bn * 64 + tx * 4;
    #pragma unroll
    for (int i = 0; i < 8; i++) {
        size_t off = (size_t)(rowbase + i) * Nn + colbase;
        #pragma unroll
        for (int j = 0; j < 4; j++) {
            float v = acc[i][j];
            if (EPI != 0) v += bias[colbase + j];
            if (EPI == 2) v = 0.5f * v * (1.0f + erff(v * 0.70710678118654752f));
            if (EPI == 1) v += res[off + j];
            C[off + j] = v;
        }
    }
}

// ---------------------------------------------------------------------------
// Window attention: one block per (window, head). All of q,k,v,S in SMEM.
// qkv layout per token (576): [3][HEADS][HD]
// ---------------------------------------------------------------------------
__global__ __launch_bounds__(256) void attn_kernel(
    const float* __restrict__ qkv, const float* __restrict__ bias_table,
    const int* __restrict__ rel_index, float* __restrict__ out)
{
    int b = blockIdx.x / HEADS;
    int h = blockIdx.x % HEADS;

    __shared__ float sq[NT * HD], sk[NT * HD], sv[NT * HD];
    __shared__ float sS[NT * NT];

    const float* base = qkv + (size_t)b * NT * (3 * DIM);
    for (int idx = threadIdx.x; idx < NT * HD; idx += blockDim.x) {
        int n = idx >> 5, d = idx & 31;
        const float* tp = base + n * (3 * DIM) + h * HD + d;
        sq[idx] = tp[0];
        sk[idx] = tp[DIM];
        sv[idx] = tp[2 * DIM];
    }
    for (int idx = threadIdx.x; idx < NT * NT; idx += blockDim.x)
        sS[idx] = bias_table[rel_index[idx] * HEADS + h];
    __syncthreads();

    const float scale = 0.17677669529663687f;  // 32^-0.5
    for (int idx = threadIdx.x; idx < NT * NT; idx += blockDim.x) {
        int i = idx / NT, j = idx - i * NT;
        float s = 0.f;
        #pragma unroll
        for (int d = 0; d < HD; d++) s += sq[i * HD + d] * sk[j * HD + d];
        sS[idx] = s * scale + sS[idx];
    }
    __syncthreads();

    if (threadIdx.x < NT) {
        int i = threadIdx.x;
        float m = -1e30f;
        for (int j = 0; j < NT; j++) m = fmaxf(m, sS[i * NT + j]);
        float sum = 0.f;
        for (int j = 0; j < NT; j++) {
            float e = expf(sS[i * NT + j] - m);
            sS[i * NT + j] = e;
            sum += e;
        }
        float inv = 1.0f / sum;
        for (int j = 0; j < NT; j++) sS[i * NT + j] *= inv;
    }
    __syncthreads();

    for (int idx = threadIdx.x; idx < NT * HD; idx += blockDim.x) {
        int i = idx >> 5, d = idx & 31;
        float o = 0.f;
        #pragma unroll
        for (int j = 0; j < NT; j++) o += sS[i * NT + j] * sv[j * HD + d];
        out[((size_t)b * NT + i) * DIM + h * HD + d] = o;
    }
}

// ---------------------------------------------------------------------------
// Launch
// ---------------------------------------------------------------------------
extern "C" void kernel_launch(void* const* d_in, const int* in_sizes, int n_in,
                              void* d_out, int out_size)
{
    const float* x          = (const float*)d_in[0];
    const float* ln1_g      = (const float*)d_in[1];
    const float* ln1_b      = (const float*)d_in[2];
    const float* qkv_w      = (const float*)d_in[3];
    const float* proj_w     = (const float*)d_in[4];
    const float* proj_b     = (const float*)d_in[5];
    const float* bias_table = (const float*)d_in[6];
    const float* ln2_g      = (const float*)d_in[7];
    const float* ln2_b      = (const float*)d_in[8];
    const float* fc1_w      = (const float*)d_in[9];
    const float* fc1_b      = (const float*)d_in[10];
    const float* fc2_w      = (const float*)d_in[11];
    const float* fc2_b      = (const float*)d_in[12];
    const int*   rel_index  = (const int*)d_in[13];
    float* out = (float*)d_out;

    float *buf192, *big;
    cudaGetSymbolAddress((void**)&buf192, g_buf192);
    cudaGetSymbolAddress((void**)&big, g_big);

    // 1) xn = LN1(x)
    ln_kernel<<<MROWS, DIM>>>(x, ln1_g, ln1_b, buf192);

    // 2) qkv = xn @ qkv_w   (M=200704, N=576, K=192)
    {
        dim3 grid(576 / 64, MROWS / 128);
        gemm_kernel<0><<<grid, 256>>>(buf192, qkv_w, nullptr, nullptr, big,
                                      MROWS, 576, DIM);
    }

    // 3) attention -> buf192 (xn dead)
    attn_kernel<<<BW * HEADS, 256>>>(big, bias_table, rel_index, buf192);

    // 4) y = x + attn @ proj_w + proj_b  -> d_out
    {
        dim3 grid(DIM / 64, MROWS / 128);
        gemm_kernel<1><<<grid, 256>>>(buf192, proj_w, proj_b, x, out,
                                      MROWS, DIM, DIM);
    }

    // 5) h = LN2(y) -> buf192
    ln_kernel<<<MROWS, DIM>>>(out, ln2_g, ln2_b, buf192);

    // 6) hidden = gelu(h @ fc1_w + fc1_b) -> big
    {
        dim3 grid(HIDDEN / 64, MROWS / 128);
        gemm_kernel<2><<<grid, 256>>>(buf192, fc1_w, fc1_b, nullptr, big,
                                      MROWS, HIDDEN, DIM);
    }

    // 7) out = y + hidden @ fc2_w + fc2_b  (in-place residual on d_out)
    {
        dim3 grid(DIM / 64, MROWS / 128);
        gemm_kernel<1><<<grid, 256>>>(big, fc2_w, fc2_b, out, out,
                                      MROWS, DIM, HIDDEN);
    }
}

// round 4
// speedup vs baseline: 1.4780x; 1.4780x over previous
#include <cuda_runtime.h>
#include <cuda_bf16.h>
#include <math.h>
#include <stdint.h>

#define BW    4096
#define NTOK  49
#define DIM   192
#define HEADS 6
#define HD    32
#define HIDDEN 768
#define MROWS (BW * NTOK)   // 200704

// ---------------------------------------------------------------------------
// Scratch (allocation-free, __device__ globals)
// ---------------------------------------------------------------------------
__device__ __nv_bfloat16 g_h192[(size_t)MROWS * DIM];
__device__ __nv_bfloat16 g_l192[(size_t)MROWS * DIM];
__device__ __nv_bfloat16 g_h768[(size_t)MROWS * HIDDEN];
__device__ __nv_bfloat16 g_l768[(size_t)MROWS * HIDDEN];
__device__ float g_qkv[(size_t)MROWS * 3 * DIM];

// transposed (N,K) + hi/lo-split weights
__device__ __nv_bfloat16 g_wqkv_h[3 * DIM * DIM], g_wqkv_l[3 * DIM * DIM];
__device__ __nv_bfloat16 g_wprj_h[DIM * DIM],     g_wprj_l[DIM * DIM];
__device__ __nv_bfloat16 g_wfc1_h[DIM * HIDDEN],  g_wfc1_l[DIM * HIDDEN];
__device__ __nv_bfloat16 g_wfc2_h[HIDDEN * DIM],  g_wfc2_l[HIDDEN * DIM];

// ---------------------------------------------------------------------------
// helpers
// ---------------------------------------------------------------------------
__device__ __forceinline__ uint32_t smem_u32(const void* p) {
    uint32_t a;
    asm("{ .reg .u64 t; cvta.to.shared.u64 t, %1; cvt.u32.u64 %0, t; }" : "=r"(a) : "l"(p));
    return a;
}
__device__ __forceinline__ void cpa16(uint32_t dst, const void* src) {
    asm volatile("cp.async.cg.shared.global [%0], [%1], 16;" :: "r"(dst), "l"(src));
}
__device__ __forceinline__ void cp_commit() {
    asm volatile("cp.async.commit_group;" ::: "memory");
}
__device__ __forceinline__ void cp_wait1() {
    asm volatile("cp.async.wait_group 1;" ::: "memory");
}
__device__ __forceinline__ void ldmx4(uint32_t* r, uint32_t addr) {
    asm volatile("ldmatrix.sync.aligned.m8n8.x4.shared.b16 {%0,%1,%2,%3}, [%4];"
                 : "=r"(r[0]), "=r"(r[1]), "=r"(r[2]), "=r"(r[3]) : "r"(addr));
}
__device__ __forceinline__ void mma_bf16(float* c, const uint32_t* a,
                                         uint32_t b0, uint32_t b1) {
    asm volatile(
        "mma.sync.aligned.m16n8k16.row.col.f32.bf16.bf16.f32 "
        "{%0,%1,%2,%3}, {%4,%5,%6,%7}, {%8,%9}, {%0,%1,%2,%3};"
        : "+f"(c[0]), "+f"(c[1]), "+f"(c[2]), "+f"(c[3])
        : "r"(a[0]), "r"(a[1]), "r"(a[2]), "r"(a[3]), "r"(b0), "r"(b1));
}

// ---------------------------------------------------------------------------
// Weight prep: transpose (K,N)->(N,K) and split fp32 -> bf16 hi/lo
// ---------------------------------------------------------------------------
__global__ void prep_w(const float* __restrict__ W, __nv_bfloat16* __restrict__ Wh,
                       __nv_bfloat16* __restrict__ Wl, int K, int N)
{
    int idx = blockIdx.x * blockDim.x + threadIdx.x;
    if (idx >= K * N) return;
    int k = idx / N, n = idx - k * N;
    float w = W[idx];
    __nv_bfloat16 h = __float2bfloat16(w);
    Wh[(size_t)n * K + k] = h;
    Wl[(size_t)n * K + k] = __float2bfloat16(w - __bfloat162float(h));
}

// ---------------------------------------------------------------------------
// LayerNorm -> bf16 hi/lo
// ---------------------------------------------------------------------------
__global__ __launch_bounds__(DIM) void ln_kernel(
    const float* __restrict__ x, const float* __restrict__ g,
    const float* __restrict__ b, __nv_bfloat16* __restrict__ oh,
    __nv_bfloat16* __restrict__ ol)
{
    int row = blockIdx.x;
    int t = threadIdx.x;
    float v = x[(size_t)row * DIM + t];
    float s = v, s2 = v * v;
    #pragma unroll
    for (int o = 16; o > 0; o >>= 1) {
        s  += __shfl_down_sync(0xffffffffu, s,  o);
        s2 += __shfl_down_sync(0xffffffffu, s2, o);
    }
    __shared__ float r0[6], r1[6];
    if ((t & 31) == 0) { r0[t >> 5] = s; r1[t >> 5] = s2; }
    __syncthreads();
    if (t == 0) {
        float a = 0.f, c = 0.f;
        #pragma unroll
        for (int i = 0; i < 6; i++) { a += r0[i]; c += r1[i]; }
        r0[0] = a * (1.0f / DIM); r1[0] = c * (1.0f / DIM);
    }
    __syncthreads();
    float mu = r0[0];
    float var = r1[0] - mu * mu;
    float y = (v - mu) * rsqrtf(var + 1e-5f) * g[t] + b[t];
    __nv_bfloat16 h = __float2bfloat16(y);
    size_t o = (size_t)row * DIM + t;
    oh[o] = h;
    ol[o] = __float2bfloat16(y - __bfloat162float(h));
}

// ---------------------------------------------------------------------------
// Split-bf16 HMMA GEMM: C = A @ W^T (+epilogue)
// A: (M,K) hi/lo row-major. W: (N,K) hi/lo row-major.
// Block tile 128x64, 256 threads (8 warps of 32x32), K-step 32,
// cp.async double-buffered, XOR-swizzled 16B chunks for ldmatrix.
// EPI: 0 none->Cf | 1 bias+res->Cf | 2 bias+gelu->Chi/Clo
// ---------------------------------------------------------------------------
#define BUF_BYTES 24576   // AH 8K + AL 8K + BH 4K + BL 4K
#define GEMM_SMEM (2 * BUF_BYTES)

template <int N_TOTAL, int K_TOTAL, int EPI>
__global__ __launch_bounds__(256) void tc_gemm(
    const __nv_bfloat16* __restrict__ Ahi, const __nv_bfloat16* __restrict__ Alo,
    const __nv_bfloat16* __restrict__ Bhi, const __nv_bfloat16* __restrict__ Blo,
    const float* __restrict__ bias, const float* __restrict__ res,
    float* __restrict__ Cf, __nv_bfloat16* __restrict__ Chi,
    __nv_bfloat16* __restrict__ Clo)
{
    constexpr int KSTEPS = K_TOTAL / 32;
    constexpr uint32_t O_AL = 8192, O_BH = 16384, O_BL = 20480;

    extern __shared__ char smem[];
    uint32_t sb = smem_u32(smem);
    int tid = threadIdx.x, lane = tid & 31, wid = tid >> 5;
    int wm = wid & 3, wn = wid >> 2;
    size_t rowbase = (size_t)blockIdx.y * 128;
    int colbase = blockIdx.x * 64;

    // ---- async tile loader for k-step s into buffer buf ----
    auto load_step = [&](int s, int buf) {
        uint32_t base = sb + buf * BUF_BYTES;
        #pragma unroll
        for (int j = 0; j < 2; j++) {
            int id = tid * 2 + j;
            int r = id >> 2, kg = id & 3;
            uint32_t soff = r * 64 + ((kg ^ (r & 3)) << 4);
            size_t g = (rowbase + r) * K_TOTAL + s * 32 + kg * 8;
            cpa16(base + soff, Ahi + g);
            cpa16(base + O_AL + soff, Alo + g);
        }
        {
            int r = tid >> 2, kg = tid & 3;
            uint32_t soff = r * 64 + ((kg ^ (r & 3)) << 4);
            size_t g = (size_t)(colbase + r) * K_TOTAL + s * 32 + kg * 8;
            cpa16(base + O_BH + soff, Bhi + g);
            cpa16(base + O_BL + soff, Blo + g);
        }
    };

    // ---- per-lane ldmatrix offsets (same for hi/lo) ----
    uint32_t aoff[2][2], boff[2][2];
    #pragma unroll
    for (int mt = 0; mt < 2; mt++)
        #pragma unroll
        for (int kk = 0; kk < 2; kk++) {
            int ra = wm * 32 + mt * 16 + (lane & 15);
            int kga = kk * 2 + (lane >> 4);
            aoff[mt][kk] = ra * 64 + ((kga ^ (ra & 3)) << 4);
        }
    #pragma unroll
    for (int np = 0; np < 2; np++)
        #pragma unroll
        for (int kk = 0; kk < 2; kk++) {
            int nb = wn * 32 + np * 16 + (lane & 7) + ((lane >> 4) << 3);
            int kgb = kk * 2 + ((lane >> 3) & 1);
            boff[np][kk] = nb * 64 + ((kgb ^ (nb & 3)) << 4);
        }

    float acc[2][4][4] = {};

    load_step(0, 0);
    cp_commit();

    for (int s = 0; s < KSTEPS; s++) {
        if (s + 1 < KSTEPS) load_step(s + 1, (s + 1) & 1);
        cp_commit();
        cp_wait1();
        __syncthreads();

        uint32_t base = sb + (s & 1) * BUF_BYTES;
        #pragma unroll
        for (int kk = 0; kk < 2; kk++) {
            uint32_t ah[2][4], al[2][4], bh[2][4], bl[2][4];
            #pragma unroll
            for (int mt = 0; mt < 2; mt++) {
                ldmx4(ah[mt], base + aoff[mt][kk]);
                ldmx4(al[mt], base + O_AL + aoff[mt][kk]);
            }
            #pragma unroll
            for (int np = 0; np < 2; np++) {
                ldmx4(bh[np], base + O_BH + boff[np][kk]);
                ldmx4(bl[np], base + O_BL + boff[np][kk]);
            }
            #pragma unroll
            for (int mt = 0; mt < 2; mt++)
                #pragma unroll
                for (int nt = 0; nt < 4; nt++) {
                    int np = nt >> 1, half = (nt & 1) * 2;
                    mma_bf16(acc[mt][nt], ah[mt], bh[np][half], bh[np][half + 1]);
                    mma_bf16(acc[mt][nt], ah[mt], bl[np][half], bl[np][half + 1]);
                    mma_bf16(acc[mt][nt], al[mt], bh[np][half], bh[np][half + 1]);
                }
        }
        __syncthreads();
    }

    // ---- epilogue ----
    #pragma unroll
    for (int mt = 0; mt < 2; mt++) {
        size_t r0 = rowbase + wm * 32 + mt * 16 + (lane >> 2);
        #pragma unroll
        for (int nt = 0; nt < 4; nt++) {
            int c = colbase + wn * 32 + nt * 8 + (lane & 3) * 2;
            #pragma unroll
            for (int half = 0; half < 2; half++) {
                size_t row = r0 + half * 8;
                float v0 = acc[mt][nt][half * 2];
                float v1 = acc[mt][nt][half * 2 + 1];
                if (EPI >= 1) { v0 += bias[c]; v1 += bias[c + 1]; }
                if (EPI == 2) {
                    v0 = 0.5f * v0 * (1.0f + erff(v0 * 0.70710678118654752f));
                    v1 = 0.5f * v1 * (1.0f + erff(v1 * 0.70710678118654752f));
                    __nv_bfloat16 h0 = __float2bfloat16(v0);
                    __nv_bfloat16 h1 = __float2bfloat16(v1);
                    __nv_bfloat162 hv; hv.x = h0; hv.y = h1;
                    __nv_bfloat162 lv;
                    lv.x = __float2bfloat16(v0 - __bfloat162float(h0));
                    lv.y = __float2bfloat16(v1 - __bfloat162float(h1));
                    *(__nv_bfloat162*)(Chi + row * N_TOTAL + c) = hv;
                    *(__nv_bfloat162*)(Clo + row * N_TOTAL + c) = lv;
                } else {
                    if (EPI == 1) {
                        const float2 rv = *(const float2*)(res + row * N_TOTAL + c);
                        v0 += rv.x; v1 += rv.y;
                    }
                    float2 ov; ov.x = v0; ov.y = v1;
                    *(float2*)(Cf + row * N_TOTAL + c) = ov;
                }
            }
        }
    }
}

// ---------------------------------------------------------------------------
// Window attention: one block per (window, head). Outputs bf16 hi/lo.
// ---------------------------------------------------------------------------
__global__ __launch_bounds__(256) void attn_kernel(
    const float* __restrict__ qkv, const float* __restrict__ bias_table,
    const int* __restrict__ rel_index, __nv_bfloat16* __restrict__ oh,
    __nv_bfloat16* __restrict__ ol)
{
    int b = blockIdx.x / HEADS;
    int h = blockIdx.x % HEADS;

    __shared__ float sq[NTOK * HD], sk[NTOK * HD], sv[NTOK * HD];
    __shared__ float sS[NTOK * NTOK];

    const float* base = qkv + (size_t)b * NTOK * (3 * DIM);
    for (int idx = threadIdx.x; idx < NTOK * HD; idx += blockDim.x) {
        int n = idx >> 5, d = idx & 31;
        const float* tp = base + n * (3 * DIM) + h * HD + d;
        sq[idx] = tp[0];
        sk[idx] = tp[DIM];
        sv[idx] = tp[2 * DIM];
    }
    for (int idx = threadIdx.x; idx < NTOK * NTOK; idx += blockDim.x)
        sS[idx] = bias_table[rel_index[idx] * HEADS + h];
    __syncthreads();

    const float scale = 0.17677669529663687f;
    for (int idx = threadIdx.x; idx < NTOK * NTOK; idx += blockDim.x) {
        int i = idx / NTOK, j = idx - i * NTOK;
        float s = 0.f;
        #pragma unroll
        for (int d = 0; d < HD; d++) s += sq[i * HD + d] * sk[j * HD + d];
        sS[idx] = s * scale + sS[idx];
    }
    __syncthreads();

    if (threadIdx.x < NTOK) {
        int i = threadIdx.x;
        float m = -1e30f;
        for (int j = 0; j < NTOK; j++) m = fmaxf(m, sS[i * NTOK + j]);
        float sum = 0.f;
        for (int j = 0; j < NTOK; j++) {
            float e = expf(sS[i * NTOK + j] - m);
            sS[i * NTOK + j] = e;
            sum += e;
        }
        float inv = 1.0f / sum;
        for (int j = 0; j < NTOK; j++) sS[i * NTOK + j] *= inv;
    }
    __syncthreads();

    for (int idx = threadIdx.x; idx < NTOK * HD; idx += blockDim.x) {
        int i = idx >> 5, d = idx & 31;
        float o = 0.f;
        #pragma unroll
        for (int j = 0; j < NTOK; j++) o += sS[i * NTOK + j] * sv[j * HD + d];
        size_t oo = ((size_t)b * NTOK + i) * DIM + h * HD + d;
        __nv_bfloat16 hb = __float2bfloat16(o);
        oh[oo] = hb;
        ol[oo] = __float2bfloat16(o - __bfloat162float(hb));
    }
}

// ---------------------------------------------------------------------------
// Launch
// ---------------------------------------------------------------------------
extern "C" void kernel_launch(void* const* d_in, const int* in_sizes, int n_in,
                              void* d_out, int out_size)
{
    const float* x          = (const float*)d_in[0];
    const float* ln1_g      = (const float*)d_in[1];
    const float* ln1_b      = (const float*)d_in[2];
    const float* qkv_w      = (const float*)d_in[3];
    const float* proj_w     = (const float*)d_in[4];
    const float* proj_b     = (const float*)d_in[5];
    const float* bias_table = (const float*)d_in[6];
    const float* ln2_g      = (const float*)d_in[7];
    const float* ln2_b      = (const float*)d_in[8];
    const float* fc1_w      = (const float*)d_in[9];
    const float* fc1_b      = (const float*)d_in[10];
    const float* fc2_w      = (const float*)d_in[11];
    const float* fc2_b      = (const float*)d_in[12];
    const int*   rel_index  = (const int*)d_in[13];
    float* out = (float*)d_out;

    __nv_bfloat16 *h192, *l192, *h768, *l768;
    __nv_bfloat16 *wqh, *wql, *wph, *wpl, *w1h, *w1l, *w2h, *w2l;
    float* qkv;
    cudaGetSymbolAddress((void**)&h192, g_h192);
    cudaGetSymbolAddress((void**)&l192, g_l192);
    cudaGetSymbolAddress((void**)&h768, g_h768);
    cudaGetSymbolAddress((void**)&l768, g_l768);
    cudaGetSymbolAddress((void**)&qkv, g_qkv);
    cudaGetSymbolAddress((void**)&wqh, g_wqkv_h);
    cudaGetSymbolAddress((void**)&wql, g_wqkv_l);
    cudaGetSymbolAddress((void**)&wph, g_wprj_h);
    cudaGetSymbolAddress((void**)&wpl, g_wprj_l);
    cudaGetSymbolAddress((void**)&w1h, g_wfc1_h);
    cudaGetSymbolAddress((void**)&w1l, g_wfc1_l);
    cudaGetSymbolAddress((void**)&w2h, g_wfc2_h);
    cudaGetSymbolAddress((void**)&w2l, g_wfc2_l);

    cudaFuncSetAttribute(tc_gemm<576, 192, 0>, cudaFuncAttributeMaxDynamicSharedMemorySize, GEMM_SMEM);
    cudaFuncSetAttribute(tc_gemm<192, 192, 1>, cudaFuncAttributeMaxDynamicSharedMemorySize, GEMM_SMEM);
    cudaFuncSetAttribute(tc_gemm<768, 192, 2>, cudaFuncAttributeMaxDynamicSharedMemorySize, GEMM_SMEM);
    cudaFuncSetAttribute(tc_gemm<192, 768, 1>, cudaFuncAttributeMaxDynamicSharedMemorySize, GEMM_SMEM);

    // Weight prep (transpose + hi/lo split)
    prep_w<<<(DIM * 576 + 255) / 256, 256>>>(qkv_w, wqh, wql, DIM, 576);
    prep_w<<<(DIM * DIM + 255) / 256, 256>>>(proj_w, wph, wpl, DIM, DIM);
    prep_w<<<(DIM * HIDDEN + 255) / 256, 256>>>(fc1_w, w1h, w1l, DIM, HIDDEN);
    prep_w<<<(HIDDEN * DIM + 255) / 256, 256>>>(fc2_w, w2h, w2l, HIDDEN, DIM);

    // 1) LN1 -> hi/lo
    ln_kernel<<<MROWS, DIM>>>(x, ln1_g, ln1_b, h192, l192);

    // 2) qkv = xn @ qkv_w
    {
        dim3 grid(576 / 64, MROWS / 128);
        tc_gemm<576, 192, 0><<<grid, 256, GEMM_SMEM>>>(
            h192, l192, wqh, wql, nullptr, nullptr, qkv, nullptr, nullptr);
    }

    // 3) attention -> hi/lo
    attn_kernel<<<BW * HEADS, 256>>>(qkv, bias_table, rel_index, h192, l192);

    // 4) y = x + attn @ proj_w + proj_b -> d_out
    {
        dim3 grid(DIM / 64, MROWS / 128);
        tc_gemm<192, 192, 1><<<grid, 256, GEMM_SMEM>>>(
            h192, l192, wph, wpl, proj_b, x, out, nullptr, nullptr);
    }

    // 5) LN2 -> hi/lo
    ln_kernel<<<MROWS, DIM>>>(out, ln2_g, ln2_b, h192, l192);

    // 6) hidden = gelu(h @ fc1_w + fc1_b) -> hi/lo
    {
        dim3 grid(HIDDEN / 64, MROWS / 128);
        tc_gemm<768, 192, 2><<<grid, 256, GEMM_SMEM>>>(
            h192, l192, w1h, w1l, fc1_b, nullptr, nullptr, h768, l768);
    }

    // 7) out = y + hidden @ fc2_w + fc2_b
    {
        dim3 grid(DIM / 64, MROWS / 128);
        tc_gemm<192, 768, 1><<<grid, 256, GEMM_SMEM>>>(
            h768, l768, w2h, w2l, fc2_b, out, out, nullptr, nullptr);
    }
}

// round 6
// speedup vs baseline: 2.7271x; 1.8452x over previous
#include <cuda_runtime.h>
#include <cuda_fp16.h>
#include <math.h>
#include <stdint.h>

#define BW    4096
#define NTOK  49
#define DIM   192
#define HEADS 6
#define HD    32
#define HIDDEN 768
#define MROWS (BW * NTOK)   // 200704

// ---------------------------------------------------------------------------
// Scratch (allocation-free, __device__ globals)
// ---------------------------------------------------------------------------
__device__ __half g_act192[(size_t)MROWS * DIM];   // ln1-out -> attn-out -> ln2-out
__device__ __half g_qkvh[(size_t)MROWS * 3 * DIM]; // fp16 qkv
__device__ __half g_hid[(size_t)MROWS * HIDDEN];   // mlp hidden (fp16)

// weights: transposed (N,K), fp16 hi/lo split
__device__ __half g_wqkv_h[3 * DIM * DIM], g_wqkv_l[3 * DIM * DIM];
__device__ __half g_wprj_h[DIM * DIM],     g_wprj_l[DIM * DIM];
__device__ __half g_wfc1_h[DIM * HIDDEN],  g_wfc1_l[DIM * HIDDEN];
__device__ __half g_wfc2_h[HIDDEN * DIM],  g_wfc2_l[HIDDEN * DIM];
__device__ float  g_bias[HEADS * NTOK * NTOK];     // pre-gathered rel-pos bias

// ---------------------------------------------------------------------------
// helpers
// ---------------------------------------------------------------------------
__device__ __forceinline__ uint32_t smem_u32(const void* p) {
    uint32_t a;
    asm("{ .reg .u64 t; cvta.to.shared.u64 t, %1; cvt.u32.u64 %0, t; }" : "=r"(a) : "l"(p));
    return a;
}
__device__ __forceinline__ void cpa16(uint32_t dst, const void* src) {
    asm volatile("cp.async.cg.shared.global [%0], [%1], 16;" :: "r"(dst), "l"(src));
}
__device__ __forceinline__ void cp_commit() {
    asm volatile("cp.async.commit_group;" ::: "memory");
}
__device__ __forceinline__ void cp_wait1() {
    asm volatile("cp.async.wait_group 1;" ::: "memory");
}
__device__ __forceinline__ void ldmx4(uint32_t* r, uint32_t addr) {
    asm volatile("ldmatrix.sync.aligned.m8n8.x4.shared.b16 {%0,%1,%2,%3}, [%4];"
                 : "=r"(r[0]), "=r"(r[1]), "=r"(r[2]), "=r"(r[3]) : "r"(addr));
}
__device__ __forceinline__ void mma_f16(float* c, const uint32_t* a,
                                        uint32_t b0, uint32_t b1) {
    asm volatile(
        "mma.sync.aligned.m16n8k16.row.col.f32.f16.f16.f32 "
        "{%0,%1,%2,%3}, {%4,%5,%6,%7}, {%8,%9}, {%0,%1,%2,%3};"
        : "+f"(c[0]), "+f"(c[1]), "+f"(c[2]), "+f"(c[3])
        : "r"(a[0]), "r"(a[1]), "r"(a[2]), "r"(a[3]), "r"(b0), "r"(b1));
}

// ---------------------------------------------------------------------------
// Weight prep: transpose (K,N)->(N,K), split fp32 -> fp16 hi/lo
// ---------------------------------------------------------------------------
__global__ void prep_w(const float* __restrict__ W, __half* __restrict__ Wh,
                       __half* __restrict__ Wl, int K, int N)
{
    int idx = blockIdx.x * blockDim.x + threadIdx.x;
    if (idx >= K * N) return;
    int k = idx / N, n = idx - k * N;
    float w = W[idx];
    __half h = __float2half_rn(w);
    Wh[(size_t)n * K + k] = h;
    Wl[(size_t)n * K + k] = __float2half_rn(w - __half2float(h));
}

// pre-gather relative-position bias: g_bias[h][i*NTOK+j]
__global__ void prep_bias(const float* __restrict__ table, const int* __restrict__ ridx,
                          float* __restrict__ out)
{
    int idx = blockIdx.x * blockDim.x + threadIdx.x;
    if (idx >= HEADS * NTOK * NTOK) return;
    int h = idx / (NTOK * NTOK), ij = idx % (NTOK * NTOK);
    out[idx] = table[ridx[ij] * HEADS + h];
}

// ---------------------------------------------------------------------------
// LayerNorm -> fp16. One block (192 threads) per token row.
// ---------------------------------------------------------------------------
__global__ __launch_bounds__(DIM) void ln_kernel(
    const float* __restrict__ x, const float* __restrict__ g,
    const float* __restrict__ b, __half* __restrict__ o)
{
    int row = blockIdx.x;
    int t = threadIdx.x;
    float v = x[(size_t)row * DIM + t];
    float s = v, s2 = v * v;
    #pragma unroll
    for (int of = 16; of > 0; of >>= 1) {
        s  += __shfl_down_sync(0xffffffffu, s,  of);
        s2 += __shfl_down_sync(0xffffffffu, s2, of);
    }
    __shared__ float r0[6], r1[6];
    if ((t & 31) == 0) { r0[t >> 5] = s; r1[t >> 5] = s2; }
    __syncthreads();
    if (t == 0) {
        float a = 0.f, c = 0.f;
        #pragma unroll
        for (int i = 0; i < 6; i++) { a += r0[i]; c += r1[i]; }
        r0[0] = a * (1.0f / DIM); r1[0] = c * (1.0f / DIM);
    }
    __syncthreads();
    float mu = r0[0];
    float var = r1[0] - mu * mu;
    float y = (v - mu) * rsqrtf(var + 1e-5f) * g[t] + b[t];
    o[(size_t)row * DIM + t] = __float2half_rn(y);
}

// ---------------------------------------------------------------------------
// fp16 HMMA GEMM with weight hi/lo split: C = A @ (Whi + Wlo)^T (+epilogue)
// A: (M,K) fp16 row-major (single). W: (N,K) fp16 hi/lo row-major.
// Block tile 128x192, 512 threads (16 warps of 32x48), K-step 32,
// 3-stage cp.async pipeline, one sync per step, XOR-swizzled ldmatrix.
// EPI: 0 -> fp16 Ch | 1 bias+res -> fp32 Cf | 2 bias+gelu -> fp16 Ch
// ---------------------------------------------------------------------------
#define STAGE   32768u  // A 8K + Bhi 12K + Blo 12K
#define O_BH    8192u
#define O_BL    20480u
#define GEMM_SMEM (3 * 32768)

template <int N_TOTAL, int K_TOTAL, int EPI>
__global__ __launch_bounds__(512, 1) void tc_gemm(
    const __half* __restrict__ A,
    const __half* __restrict__ Bh, const __half* __restrict__ Bl,
    const float* __restrict__ bias, const float* __restrict__ res,
    float* __restrict__ Cf, __half* __restrict__ Ch)
{
    constexpr int KSTEPS = K_TOTAL / 32;

    extern __shared__ char smem[];
    uint32_t sb = smem_u32(smem);
    int tid = threadIdx.x, lane = tid & 31, wid = tid >> 5;
    int wm = wid & 3, wn = wid >> 2;          // 4 x 4 warp grid
    size_t rowbase = (size_t)blockIdx.y * 128;
    int colbase = blockIdx.x * 192;

    auto load_stage = [&](int s) {
        uint32_t base = sb + (uint32_t)(s % 3) * STAGE;
        {   // A: 128 rows x 4 chunks of 16B
            int r = tid >> 2, kg = tid & 3;
            uint32_t soff = r * 64 + ((kg ^ (r & 3)) << 4);
            cpa16(base + soff, A + (rowbase + r) * K_TOTAL + s * 32 + kg * 8);
        }
        // B: 192 rows x 4 chunks, hi+lo
        #pragma unroll
        for (int i = tid; i < 768; i += 512) {
            int r = i >> 2, kg = i & 3;
            uint32_t soff = r * 64 + ((kg ^ (r & 3)) << 4);
            size_t g = (size_t)(colbase + r) * K_TOTAL + s * 32 + kg * 8;
            cpa16(base + O_BH + soff, Bh + g);
            cpa16(base + O_BL + soff, Bl + g);
        }
    };

    // per-lane ldmatrix offsets
    uint32_t aoff[2][2], boff[3][2];
    #pragma unroll
    for (int mt = 0; mt < 2; mt++)
        #pragma unroll
        for (int kk = 0; kk < 2; kk++) {
            int ra = wm * 32 + mt * 16 + (lane & 15);
            int kga = kk * 2 + (lane >> 4);
            aoff[mt][kk] = ra * 64 + ((kga ^ (ra & 3)) << 4);
        }
    #pragma unroll
    for (int np = 0; np < 3; np++)
        #pragma unroll
        for (int kk = 0; kk < 2; kk++) {
            int nb = wn * 48 + np * 16 + (lane & 7) + ((lane >> 4) << 3);
            int kgb = kk * 2 + ((lane >> 3) & 1);
            boff[np][kk] = nb * 64 + ((kgb ^ (nb & 3)) << 4);
        }

    float acc[2][6][4] = {};

    load_stage(0); cp_commit();
    load_stage(1); cp_commit();

    for (int s = 0; s < KSTEPS; s++) {
        cp_wait1();
        __syncthreads();
        uint32_t base = sb + (uint32_t)(s % 3) * STAGE;
        #pragma unroll
        for (int kk = 0; kk < 2; kk++) {
            uint32_t ah[2][4];
            ldmx4(ah[0], base + aoff[0][kk]);
            ldmx4(ah[1], base + aoff[1][kk]);
            #pragma unroll
            for (int np = 0; np < 3; np++) {
                uint32_t bh[4], bl[4];
                ldmx4(bh, base + O_BH + boff[np][kk]);
                ldmx4(bl, base + O_BL + boff[np][kk]);
                #pragma unroll
                for (int mt = 0; mt < 2; mt++) {
                    mma_f16(acc[mt][np * 2],     ah[mt], bh[0], bh[1]);
                    mma_f16(acc[mt][np * 2],     ah[mt], bl[0], bl[1]);
                    mma_f16(acc[mt][np * 2 + 1], ah[mt], bh[2], bh[3]);
                    mma_f16(acc[mt][np * 2 + 1], ah[mt], bl[2], bl[3]);
                }
            }
        }
        if (s + 2 < KSTEPS) load_stage(s + 2);
        cp_commit();
    }

    // ---- epilogue ----
    #pragma unroll
    for (int mt = 0; mt < 2; mt++) {
        size_t rbase = rowbase + wm * 32 + mt * 16 + (lane >> 2);
        #pragma unroll
        for (int nt = 0; nt < 6; nt++) {
            int c = colbase + wn * 48 + nt * 8 + (lane & 3) * 2;
            #pragma unroll
            for (int half = 0; half < 2; half++) {
                size_t row = rbase + half * 8;
                float v0 = acc[mt][nt][half * 2];
                float v1 = acc[mt][nt][half * 2 + 1];
                if (EPI >= 1) { v0 += bias[c]; v1 += bias[c + 1]; }
                if (EPI == 2) {
                    v0 = 0.5f * v0 * (1.0f + erff(v0 * 0.70710678118654752f));
                    v1 = 0.5f * v1 * (1.0f + erff(v1 * 0.70710678118654752f));
                }
                if (EPI == 1) {
                    const float2 rv = *(const float2*)(res + row * N_TOTAL + c);
                    float2 ov; ov.x = v0 + rv.x; ov.y = v1 + rv.y;
                    *(float2*)(Cf + row * N_TOTAL + c) = ov;
                } else {
                    __half2 hv; hv.x = __float2half_rn(v0); hv.y = __float2half_rn(v1);
                    *(__half2*)(Ch + row * N_TOTAL + c) = hv;
                }
            }
        }
    }
}

// ---------------------------------------------------------------------------
// Window attention: one block per (window, head). fp16 in / fp16 out.
// sk padded to stride 33 (bank-conflict-free QK^T), warp-per-row softmax.
// ---------------------------------------------------------------------------
#define SKP 33
__global__ __launch_bounds__(256) void attn_kernel(
    const __half* __restrict__ qkv, const float* __restrict__ bias,
    __half* __restrict__ out)
{
    int b = blockIdx.x / HEADS;
    int h = blockIdx.x % HEADS;
    int tid = threadIdx.x, lane = tid & 31, wid = tid >> 5;

    __shared__ float sq[NTOK * HD], sk[NTOK * SKP], sv[NTOK * HD];
    __shared__ float sS[NTOK * NTOK];

    const __half* base = qkv + (size_t)b * NTOK * (3 * DIM);
    for (int idx = tid; idx < NTOK * HD; idx += 256) {
        int n = idx >> 5, d = idx & 31;
        const __half* tp = base + n * (3 * DIM) + h * HD + d;
        sq[idx]          = __half2float(tp[0]);
        sk[n * SKP + d]  = __half2float(tp[DIM]);
        sv[idx]          = __half2float(tp[2 * DIM]);
    }
    const float* bb = bias + h * NTOK * NTOK;
    __syncthreads();

    const float scale = 0.17677669529663687f;
    for (int idx = tid; idx < NTOK * NTOK; idx += 256) {
        int i = idx / NTOK, j = idx - i * NTOK;
        float s = 0.f;
        #pragma unroll
        for (int d = 0; d < HD; d++) s += sq[i * HD + d] * sk[j * SKP + d];
        sS[idx] = s * scale + bb[idx];
    }
    __syncthreads();

    // warp-per-row softmax
    for (int i = wid; i < NTOK; i += 8) {
        float v0 = (lane < NTOK) ? sS[i * NTOK + lane] : -1e30f;
        float v1 = (lane + 32 < NTOK) ? sS[i * NTOK + lane + 32] : -1e30f;
        float m = fmaxf(v0, v1);
        #pragma unroll
        for (int o = 16; o > 0; o >>= 1) m = fmaxf(m, __shfl_xor_sync(0xffffffffu, m, o));
        float e0 = (lane < NTOK) ? __expf(v0 - m) : 0.f;
        float e1 = (lane + 32 < NTOK) ? __expf(v1 - m) : 0.f;
        float sum = e0 + e1;
        #pragma unroll
        for (int o = 16; o > 0; o >>= 1) sum += __shfl_xor_sync(0xffffffffu, sum, o);
        float inv = 1.0f / sum;
        if (lane < NTOK) sS[i * NTOK + lane] = e0 * inv;
        if (lane + 32 < NTOK) sS[i * NTOK + lane + 32] = e1 * inv;
    }
    __syncthreads();

    for (int idx = tid; idx < NTOK * HD; idx += 256) {
        int i = idx >> 5, d = idx & 31;
        float o = 0.f;
        #pragma unroll
        for (int j = 0; j < NTOK; j++) o += sS[i * NTOK + j] * sv[j * HD + d];
        out[((size_t)b * NTOK + i) * DIM + h * HD + d] = __float2half_rn(o);
    }
}

// ---------------------------------------------------------------------------
// Launch
// ---------------------------------------------------------------------------
extern "C" void kernel_launch(void* const* d_in, const int* in_sizes, int n_in,
                              void* d_out, int out_size)
{
    const float* x          = (const float*)d_in[0];
    const float* ln1_g      = (const float*)d_in[1];
    const float* ln1_b      = (const float*)d_in[2];
    const float* qkv_w      = (const float*)d_in[3];
    const float* proj_w     = (const float*)d_in[4];
    const float* proj_b     = (const float*)d_in[5];
    const float* bias_table = (const float*)d_in[6];
    const float* ln2_g      = (const float*)d_in[7];
    const float* ln2_b      = (const float*)d_in[8];
    const float* fc1_w      = (const float*)d_in[9];
    const float* fc1_b      = (const float*)d_in[10];
    const float* fc2_w      = (const float*)d_in[11];
    const float* fc2_b      = (const float*)d_in[12];
    const int*   rel_index  = (const int*)d_in[13];
    float* out = (float*)d_out;

    __half *act, *qkvh, *hid;
    __half *wqh, *wql, *wph, *wpl, *w1h, *w1l, *w2h, *w2l;
    float* biasg;
    cudaGetSymbolAddress((void**)&act, g_act192);
    cudaGetSymbolAddress((void**)&qkvh, g_qkvh);
    cudaGetSymbolAddress((void**)&hid, g_hid);
    cudaGetSymbolAddress((void**)&wqh, g_wqkv_h);
    cudaGetSymbolAddress((void**)&wql, g_wqkv_l);
    cudaGetSymbolAddress((void**)&wph, g_wprj_h);
    cudaGetSymbolAddress((void**)&wpl, g_wprj_l);
    cudaGetSymbolAddress((void**)&w1h, g_wfc1_h);
    cudaGetSymbolAddress((void**)&w1l, g_wfc1_l);
    cudaGetSymbolAddress((void**)&w2h, g_wfc2_h);
    cudaGetSymbolAddress((void**)&w2l, g_wfc2_l);
    cudaGetSymbolAddress((void**)&biasg, g_bias);

    cudaFuncSetAttribute(tc_gemm<576, 192, 0>, cudaFuncAttributeMaxDynamicSharedMemorySize, GEMM_SMEM);
    cudaFuncSetAttribute(tc_gemm<192, 192, 1>, cudaFuncAttributeMaxDynamicSharedMemorySize, GEMM_SMEM);
    cudaFuncSetAttribute(tc_gemm<768, 192, 2>, cudaFuncAttributeMaxDynamicSharedMemorySize, GEMM_SMEM);
    cudaFuncSetAttribute(tc_gemm<192, 768, 1>, cudaFuncAttributeMaxDynamicSharedMemorySize, GEMM_SMEM);

    // prep
    prep_w<<<(DIM * 576 + 255) / 256, 256>>>(qkv_w, wqh, wql, DIM, 576);
    prep_w<<<(DIM * DIM + 255) / 256, 256>>>(proj_w, wph, wpl, DIM, DIM);
    prep_w<<<(DIM * HIDDEN + 255) / 256, 256>>>(fc1_w, w1h, w1l, DIM, HIDDEN);
    prep_w<<<(HIDDEN * DIM + 255) / 256, 256>>>(fc2_w, w2h, w2l, HIDDEN, DIM);
    prep_bias<<<(HEADS * NTOK * NTOK + 255) / 256, 256>>>(bias_table, rel_index, biasg);

    // 1) LN1 -> fp16
    ln_kernel<<<MROWS, DIM>>>(x, ln1_g, ln1_b, act);

    // 2) qkv = xn @ qkv_w -> fp16
    {
        dim3 grid(3, MROWS / 128);
        tc_gemm<576, 192, 0><<<grid, 512, GEMM_SMEM>>>(
            act, wqh, wql, nullptr, nullptr, nullptr, qkvh);
    }

    // 3) attention -> fp16
    attn_kernel<<<BW * HEADS, 256>>>(qkvh, biasg, act);

    // 4) y = x + attn @ proj_w + proj_b -> d_out (fp32)
    {
        dim3 grid(1, MROWS / 128);
        tc_gemm<192, 192, 1><<<grid, 512, GEMM_SMEM>>>(
            act, wph, wpl, proj_b, x, out, nullptr);
    }

    // 5) LN2 -> fp16
    ln_kernel<<<MROWS, DIM>>>(out, ln2_g, ln2_b, act);

    // 6) hidden = gelu(h @ fc1_w + fc1_b) -> fp16
    {
        dim3 grid(4, MROWS / 128);
        tc_gemm<768, 192, 2><<<grid, 512, GEMM_SMEM>>>(
            act, w1h, w1l, fc1_b, nullptr, nullptr, hid);
    }

    // 7) out = y + hidden @ fc2_w + fc2_b
    {
        dim3 grid(1, MROWS / 128);
        tc_gemm<192, 768, 1><<<grid, 512, GEMM_SMEM>>>(
            hid, w2h, w2l, fc2_b, out, out, nullptr);
    }
}